// round 15
// baseline (speedup 1.0000x reference)
#include <cuda_runtime.h>
#include <cstdint>

#define VOCAB 81616
#define DIM 32
#define BATCH 4096

typedef unsigned long long u64;

// ---------------- pass 1 config (r10-proven: BM=256, 8 warps, 2-stage) ----------------
#define BM 256
#define BK 32
#define NSPLIT 18
#define NTILES ((VOCAB + BK - 1) / BK)        // 2551
#define TPS ((NTILES + NSPLIT - 1) / NSPLIT)  // 142
#define HALF_ROWBLOCKS 8                      // 2048 rows per half
#define P1_THREADS 256
#define P1B_CTAS (HALF_ROWBLOCKS * NSPLIT)    // 144

#define XS_STRIDE 36                          // 144B rows: 16B-aligned, bank=4r+c
#define P1_XS_BYTES (BM * XS_STRIDE * 4)      // 36864
#define P1_WS_BYTES (BK * XS_STRIDE * 4)      // 4608
#define P1_BUF (P1_XS_BYTES + P1_WS_BYTES)    // 41472
#define P1_SMEM (2 * P1_BUF)                  // 82944

// ---------------- pass 2 config (r7-proven) ----------------
#define P2_THREADS 256
#define P2_MROWS 64
#define P2_COLS 128
#define P2_JBLOCKS ((VOCAB + P2_COLS - 1) / P2_COLS)   // 638
#define P2_ROWS_PER_CTA 1024
#define P2_CHUNKS (P2_ROWS_PER_CTA / P2_MROWS)         // 16
#define P2_HALF_YB 2                                   // 2048 rows per half
#define HS_STRIDE 36
#define P2_SMEM (2 * P2_MROWS * HS_STRIDE * 4)         // 18432

// Scratch (no cudaMalloc allowed — device globals)
__device__ __align__(16) float g_partial[NSPLIT * BATCH * DIM];  // 9.4 MB
__device__ __align__(16) float g_h[BATCH * DIM];                 // 512 KB (tf32-rounded)

// ---------------- helpers ----------------
__device__ __forceinline__ float sigt(float x) {
    float t;
    asm("tanh.approx.f32 %0, %1;" : "=f"(t) : "f"(x * 0.5f));
    return fmaf(0.5f, t, 0.5f);
}

__device__ __forceinline__ unsigned smem_u32(const void* p) {
    unsigned a;
    asm("{ .reg .u64 t; cvta.to.shared.u64 t, %1; cvt.u32.u64 %0, t; }" : "=r"(a) : "l"(p));
    return a;
}

__device__ __forceinline__ void cp16z(unsigned dst, const void* src, unsigned sz) {
    asm volatile("cp.async.cg.shared.global [%0], [%1], 16, %2;" :: "r"(dst), "l"(src), "r"(sz));
}
__device__ __forceinline__ void cp4(unsigned dst, const void* src, unsigned sz) {
    asm volatile("cp.async.ca.shared.global [%0], [%1], 4, %2;" :: "r"(dst), "l"(src), "r"(sz));
}
__device__ __forceinline__ void cp16(unsigned dst, const void* src) {
    asm volatile("cp.async.ca.shared.global [%0], [%1], 16;" :: "r"(dst), "l"(src));
}
#define CP_COMMIT() asm volatile("cp.async.commit_group;")
#define CP_WAIT1()  asm volatile("cp.async.wait_group 1;")

__device__ __forceinline__ uint32_t to_tf32(float f) {
    uint32_t r;
    asm("cvt.rna.tf32.f32 %0, %1;" : "=r"(r) : "f"(f));
    return r;
}

__device__ __forceinline__ void mma_tf32(float* d, const uint32_t* a, const uint32_t* b) {
    asm("mma.sync.aligned.m16n8k8.row.col.f32.tf32.tf32.f32 "
        "{%0,%1,%2,%3}, {%4,%5,%6,%7}, {%8,%9}, {%0,%1,%2,%3};"
        : "+f"(d[0]), "+f"(d[1]), "+f"(d[2]), "+f"(d[3])
        : "r"(a[0]), "r"(a[1]), "r"(a[2]), "r"(a[3]), "r"(b[0]), "r"(b[1]));
}

// =====================================================================
// Pass 1 BODY (r10-proven tf32 mma, BM=256, double-buffered cp.async)
// =====================================================================
__device__ __forceinline__ void p1_load(unsigned sb, int buf, int tile,
                                        const float* __restrict__ X,
                                        const float* __restrict__ W,
                                        int row0, int t) {
    const int k0 = tile * BK;
    const unsigned xbase = sb + (unsigned)buf * P1_BUF;
    const unsigned wbase = xbase + P1_XS_BYTES;

    // x: 256 rows x 8 float4 -> 8 cp16 per thread; lanes 0..7 cover one row
    const int u  = t & 7;
    const int r0 = t >> 3;             // 0..31
    const int gk = k0 + 4 * u;
    const unsigned szx = (gk < VOCAB) ? 16u : 0u;
    const float* srcx = (gk < VOCAB) ? (X + (size_t)(row0 + r0) * VOCAB + gk) : X;
#pragma unroll
    for (int i = 0; i < 8; ++i) {
        int row = i * 32 + r0;
        cp16z(xbase + (unsigned)(row * XS_STRIDE + 4 * u) * 4u, srcx, szx);
        srcx += (size_t)32 * VOCAB;
    }

    // w: 32 k-rows x 32 j native [k][j]; 4 cp4 per thread
    const int j  = t & 31;
    const int kb = t >> 5;             // 0..7
#pragma unroll
    for (int i = 0; i < 4; ++i) {
        int kk = kb + i * 8;
        int g  = k0 + kk;
        unsigned sz = (g < VOCAB) ? 4u : 0u;
        const float* src = (g < VOCAB) ? (W + (size_t)g * DIM + j) : W;
        cp4(wbase + (unsigned)(kk * XS_STRIDE + j) * 4u, src, sz);
    }
}

__device__ __noinline__ void p1_body(const float* __restrict__ X,
                                     const float* __restrict__ W,
                                     char* smem, int t, int row0, int s) {
    const unsigned sb = smem_u32(smem);
    const int lane = t & 31;
    const int wid  = t >> 5;           // 0..7
    const int g    = lane >> 2;
    const int tig  = lane & 3;

    float acc[32];
#pragma unroll
    for (int i = 0; i < 32; ++i) acc[i] = 0.f;

    const int tile0 = s * TPS;
    const int tile1 = (tile0 + TPS < NTILES) ? (tile0 + TPS) : NTILES;
    const int nt_   = tile1 - tile0;

    p1_load(sb, 0, tile0, X, W, row0, t);
    CP_COMMIT();

    const int mrow = wid * 32 + g;

    for (int i = 0; i < nt_; ++i) {
        if (i + 1 < nt_) p1_load(sb, (i + 1) & 1, tile0 + i + 1, X, W, row0, t);
        CP_COMMIT();
        CP_WAIT1();
        __syncthreads();

        const float* xp = reinterpret_cast<const float*>(smem + (i & 1) * P1_BUF);
        const float* wp = reinterpret_cast<const float*>(smem + (i & 1) * P1_BUF + P1_XS_BYTES);

#pragma unroll
        for (int ks = 0; ks < 4; ++ks) {
            const int kc = ks * 8;
            uint32_t a[2][4], b[4][2];
#pragma unroll
            for (int mt = 0; mt < 2; ++mt) {
                const float* ap = xp + (mrow + mt * 16) * XS_STRIDE + kc + tig;
                a[mt][0] = to_tf32(ap[0]);
                a[mt][1] = to_tf32(ap[8 * XS_STRIDE]);
                a[mt][2] = to_tf32(ap[4]);
                a[mt][3] = to_tf32(ap[8 * XS_STRIDE + 4]);
            }
#pragma unroll
            for (int nt2 = 0; nt2 < 4; ++nt2) {
                const float* bp = wp + (kc + tig) * XS_STRIDE + nt2 * 8 + g;
                b[nt2][0] = to_tf32(bp[0]);
                b[nt2][1] = to_tf32(bp[4 * XS_STRIDE]);
            }
#pragma unroll
            for (int mt = 0; mt < 2; ++mt)
#pragma unroll
                for (int nt2 = 0; nt2 < 4; ++nt2)
                    mma_tf32(&acc[(mt * 4 + nt2) * 4], a[mt], b[nt2]);
        }
        __syncthreads();
    }

#pragma unroll
    for (int mt = 0; mt < 2; ++mt) {
#pragma unroll
        for (int nt2 = 0; nt2 < 4; ++nt2) {
            const float* d = &acc[(mt * 4 + nt2) * 4];
            int r = row0 + mrow + mt * 16;
            int c = nt2 * 8 + 2 * tig;
            float2 lo = make_float2(d[0], d[1]);
            float2 hi = make_float2(d[2], d[3]);
            *reinterpret_cast<float2*>(&g_partial[((size_t)s * BATCH + r) * DIM + c]) = lo;
            *reinterpret_cast<float2*>(&g_partial[((size_t)s * BATCH + r + 8) * DIM + c]) = hi;
        }
    }
}

// =====================================================================
// Pass 2 BODY (r7-proven tf32 mma, w-frags register-resident)
// =====================================================================
__device__ __forceinline__ void p2_load(unsigned hbase, int buf, int ib, int t) {
    const unsigned dst0 = hbase + (unsigned)buf * (P2_MROWS * HS_STRIDE * 4);
#pragma unroll
    for (int i = 0; i < 2; ++i) {
        int e   = i * P2_THREADS + t;
        int row = e >> 3;
        int q   = e & 7;
        cp16(dst0 + (unsigned)(row * HS_STRIDE + q * 4) * 4u,
             &g_h[(size_t)(ib + row) * DIM + q * 4]);
    }
}

__device__ __noinline__ void p2_body(const float* __restrict__ W,
                                     float* __restrict__ Y,
                                     char* smem, int t, int jblk, int ib0) {
    float* hs = reinterpret_cast<float*>(smem);
    const unsigned hbase = smem_u32(smem);

    const int lane = t & 31;
    const int wid  = t >> 5;
    const int wm   = wid & 3;
    const int wn   = wid >> 2;
    const int g    = lane >> 2;
    const int tig  = lane & 3;
    const int c0   = jblk * P2_COLS + wn * 64;

    uint32_t bw[8][4][2];
#pragma unroll
    for (int nt = 0; nt < 8; ++nt) {
        int j = c0 + nt * 8 + g;
        bool v = (j < VOCAB);
        const float* wr = W + (size_t)(v ? j : 0) * DIM;
#pragma unroll
        for (int ks = 0; ks < 4; ++ks) {
            bw[nt][ks][0] = to_tf32(v ? wr[ks * 8 + tig]     : 0.f);
            bw[nt][ks][1] = to_tf32(v ? wr[ks * 8 + tig + 4] : 0.f);
        }
    }

    p2_load(hbase, 0, ib0, t);
    CP_COMMIT();

    for (int c = 0; c < P2_CHUNKS; ++c) {
        if (c + 1 < P2_CHUNKS) p2_load(hbase, (c + 1) & 1, ib0 + (c + 1) * P2_MROWS, t);
        CP_COMMIT();
        CP_WAIT1();
        __syncthreads();

        const float* hb = hs + (c & 1) * (P2_MROWS * HS_STRIDE);
        float acc[8][4];
#pragma unroll
        for (int nt = 0; nt < 8; ++nt)
#pragma unroll
            for (int i = 0; i < 4; ++i) acc[nt][i] = 0.f;

#pragma unroll
        for (int ks = 0; ks < 4; ++ks) {
            uint32_t a[4];
            const float* ap = hb + (wm * 16 + g) * HS_STRIDE + ks * 8 + tig;
            a[0] = __float_as_uint(ap[0]);
            a[1] = __float_as_uint(ap[8 * HS_STRIDE]);
            a[2] = __float_as_uint(ap[4]);
            a[3] = __float_as_uint(ap[8 * HS_STRIDE + 4]);
#pragma unroll
            for (int nt = 0; nt < 8; ++nt)
                mma_tf32(acc[nt], a, bw[nt][ks]);
        }

        const size_t r0 = (size_t)(ib0 + c * P2_MROWS + wm * 16 + g);
#pragma unroll
        for (int nt = 0; nt < 8; ++nt) {
            int colb = c0 + nt * 8;
            if (colb < VOCAB) {
                int col = colb + 2 * tig;
                float2 lo = make_float2(sigt(acc[nt][0]), sigt(acc[nt][1]));
                float2 hi = make_float2(sigt(acc[nt][2]), sigt(acc[nt][3]));
                *reinterpret_cast<float2*>(&Y[r0 * VOCAB + col])       = lo;
                *reinterpret_cast<float2*>(&Y[(r0 + 8) * VOCAB + col]) = hi;
            }
        }
        __syncthreads();
    }
}

// =====================================================================
// Kernels
// =====================================================================
__global__ __launch_bounds__(P1_THREADS, 2) void pass1_half_kernel(const float* __restrict__ X,
                                                                   const float* __restrict__ W,
                                                                   int rowbase) {
    extern __shared__ char smem[];
    p1_body(X, W, smem, threadIdx.x, rowbase + blockIdx.x * BM, blockIdx.y);
}

// Mixed: first P1B_CTAS blocks run pass1 on half B; the rest run pass2 on half A.
__global__ __launch_bounds__(256, 2) void mixed_kernel(const float* __restrict__ X,
                                                       const float* __restrict__ W,
                                                       float* __restrict__ Y) {
    extern __shared__ char smem[];
    const int bx = blockIdx.x;
    if (bx < P1B_CTAS) {
        p1_body(X, W, smem, threadIdx.x, 2048 + (bx & 7) * BM, bx >> 3);
    } else {
        int idx  = bx - P1B_CTAS;
        int jblk = idx % P2_JBLOCKS;
        int yb   = idx / P2_JBLOCKS;
        p2_body(W, Y, smem, threadIdx.x, jblk, yb * P2_ROWS_PER_CTA);
    }
}

__global__ __launch_bounds__(P2_THREADS, 2) void pass2_half_kernel(const float* __restrict__ W,
                                                                   float* __restrict__ Y,
                                                                   int rowbase) {
    extern __shared__ char smem[];
    p2_body(W, Y, smem, threadIdx.x, blockIdx.x, rowbase + blockIdx.y * P2_ROWS_PER_CTA);
}

// Reduce partials + bias + sigmoid -> g_h (tf32-pre-rounded), one half.
__global__ void reduce_half_kernel(const float* __restrict__ b, int rowbase) {
    int idx = blockIdx.x * blockDim.x + threadIdx.x;
    if (idx >= 2048 * DIM) return;
    int gidx = rowbase * DIM + idx;
    float sum = b[gidx & (DIM - 1)];
#pragma unroll
    for (int s = 0; s < NSPLIT; ++s)
        sum += g_partial[(size_t)s * BATCH * DIM + gidx];
    g_h[gidx] = __uint_as_float(to_tf32(sigt(sum)));
}

// =====================================================================
extern "C" void kernel_launch(void* const* d_in, const int* in_sizes, int n_in,
                              void* d_out, int out_size) {
    const float* x = (const float*)d_in[0];  // [4096, 81616]
    const float* w = (const float*)d_in[1];  // [81616, 32]
    const float* b = (const float*)d_in[2];  // [32]
    float* y = (float*)d_out;                // [4096, 81616]

    cudaFuncSetAttribute(pass1_half_kernel, cudaFuncAttributeMaxDynamicSharedMemorySize, P1_SMEM);
    cudaFuncSetAttribute(mixed_kernel,      cudaFuncAttributeMaxDynamicSharedMemorySize, P1_SMEM);

    const int rblocks = (2048 * DIM + 255) / 256;

    // 1) pass1 on half A (rows 0..2047)
    dim3 g1(HALF_ROWBLOCKS, NSPLIT);
    pass1_half_kernel<<<g1, P1_THREADS, P1_SMEM>>>(x, w, 0);

    // 2) reduce half A
    reduce_half_kernel<<<rblocks, 256>>>(b, 0);

    // 3) mixed: pass1 half B (first 144 CTAs) + pass2 half A (1276 CTAs)
    mixed_kernel<<<P1B_CTAS + P2_JBLOCKS * P2_HALF_YB, 256, P1_SMEM>>>(x, w, y);

    // 4) reduce half B
    reduce_half_kernel<<<rblocks, 256>>>(b, 2048);

    // 5) pass2 on half B (rows 2048..4095)
    dim3 g2(P2_JBLOCKS, P2_HALF_YB);
    pass2_half_kernel<<<g2, P2_THREADS, P2_SMEM>>>(w, y, 2048);
}

// round 16
// speedup vs baseline: 1.0717x; 1.0717x over previous
#include <cuda_runtime.h>
#include <cstdint>

#define VOCAB 81616
#define DIM 32
#define BATCH 4096

typedef unsigned long long u64;

// ---------------- pass 1 config (r10-proven: BM=256, 8 warps, 2-stage, cp16) ----------------
#define BM 256
#define BK 32
#define NSPLIT 18
#define NTILES ((VOCAB + BK - 1) / BK)        // 2551
#define TPS ((NTILES + NSPLIT - 1) / NSPLIT)  // 142
#define ROWBLOCKS (BATCH / BM)                // 16
#define P1_THREADS 256

#define XS_STRIDE 36                          // 144B rows: 16B-aligned, bank=4r+c
#define P1_XS_BYTES (BM * XS_STRIDE * 4)      // 36864
#define P1_WS_BYTES (BK * XS_STRIDE * 4)      // 4608
#define P1_BUF (P1_XS_BYTES + P1_WS_BYTES)    // 41472
#define P1_SMEM (2 * P1_BUF)                  // 82944

// ---------------- pass 2 config: 4 n-tiles/warp, 3 CTAs/SM ----------------
#define P2_THREADS 256
#define P2_MROWS 64
#define P2_COLS 64                            // 2 n-warps x 32 cols
#define P2_YSPLIT 4
#define P2_CHUNKS ((BATCH / P2_YSPLIT) / P2_MROWS)  // 16
#define HS_STRIDE 36

// Scratch (no cudaMalloc allowed — device globals)
__device__ __align__(16) float g_partial[NSPLIT * BATCH * DIM];  // 9.4 MB
__device__ __align__(16) float g_h[BATCH * DIM];                 // 512 KB (tf32-rounded)

// ---------------- helpers ----------------
__device__ __forceinline__ float sigt(float x) {
    float t;
    asm("tanh.approx.f32 %0, %1;" : "=f"(t) : "f"(x * 0.5f));
    return fmaf(0.5f, t, 0.5f);
}

__device__ __forceinline__ unsigned smem_u32(const void* p) {
    unsigned a;
    asm("{ .reg .u64 t; cvta.to.shared.u64 t, %1; cvt.u32.u64 %0, t; }" : "=r"(a) : "l"(p));
    return a;
}

__device__ __forceinline__ void cp16z(unsigned dst, const void* src, unsigned sz) {
    asm volatile("cp.async.cg.shared.global [%0], [%1], 16, %2;" :: "r"(dst), "l"(src), "r"(sz));
}
__device__ __forceinline__ void cp4(unsigned dst, const void* src, unsigned sz) {
    asm volatile("cp.async.ca.shared.global [%0], [%1], 4, %2;" :: "r"(dst), "l"(src), "r"(sz));
}
__device__ __forceinline__ void cp16(unsigned dst, const void* src) {
    asm volatile("cp.async.ca.shared.global [%0], [%1], 16;" :: "r"(dst), "l"(src));
}
#define CP_COMMIT() asm volatile("cp.async.commit_group;")
#define CP_WAIT1()  asm volatile("cp.async.wait_group 1;")

__device__ __forceinline__ uint32_t to_tf32(float f) {
    uint32_t r;
    asm("cvt.rna.tf32.f32 %0, %1;" : "=r"(r) : "f"(f));
    return r;
}

__device__ __forceinline__ void mma_tf32(float* d, const uint32_t* a, const uint32_t* b) {
    asm("mma.sync.aligned.m16n8k8.row.col.f32.tf32.tf32.f32 "
        "{%0,%1,%2,%3}, {%4,%5,%6,%7}, {%8,%9}, {%0,%1,%2,%3};"
        : "+f"(d[0]), "+f"(d[1]), "+f"(d[2]), "+f"(d[3])
        : "r"(a[0]), "r"(a[1]), "r"(a[2]), "r"(a[3]), "r"(b[0]), "r"(b[1]));
}

// =====================================================================
// Pass 1 (tf32 tensor) — r10 exact (measured 259.4us, DRAM 66.3%).
// =====================================================================
__device__ __forceinline__ void p1_load(unsigned sb, int buf, int tile,
                                        const float* __restrict__ X,
                                        const float* __restrict__ W,
                                        int row0, int t) {
    const int k0 = tile * BK;
    const unsigned xbase = sb + (unsigned)buf * P1_BUF;
    const unsigned wbase = xbase + P1_XS_BYTES;

    // x: 256 rows x 8 float4 -> 8 cp16 per thread; lanes 0..7 cover one row
    const int u  = t & 7;
    const int r0 = t >> 3;             // 0..31
    const int gk = k0 + 4 * u;
    const unsigned szx = (gk < VOCAB) ? 16u : 0u;
    const float* srcx = (gk < VOCAB) ? (X + (size_t)(row0 + r0) * VOCAB + gk) : X;
#pragma unroll
    for (int i = 0; i < 8; ++i) {
        int row = i * 32 + r0;
        cp16z(xbase + (unsigned)(row * XS_STRIDE + 4 * u) * 4u, srcx, szx);
        srcx += (size_t)32 * VOCAB;
    }

    // w: 32 k-rows x 32 j, native layout ws[k][j]; 4 cp4 per thread
    const int j  = t & 31;
    const int kb = t >> 5;             // 0..7
#pragma unroll
    for (int i = 0; i < 4; ++i) {
        int kk = kb + i * 8;
        int g  = k0 + kk;
        unsigned sz = (g < VOCAB) ? 4u : 0u;
        const float* src = (g < VOCAB) ? (W + (size_t)g * DIM + j) : W;
        cp4(wbase + (unsigned)(kk * XS_STRIDE + j) * 4u, src, sz);
    }
}

__global__ __launch_bounds__(P1_THREADS, 2) void pass1_kernel(const float* __restrict__ X,
                                                              const float* __restrict__ W) {
    extern __shared__ char smem[];
    const unsigned sb = smem_u32(smem);

    const int t    = threadIdx.x;
    const int lane = t & 31;
    const int wid  = t >> 5;           // 0..7 -> m-slab
    const int g    = lane >> 2;
    const int tig  = lane & 3;
    const int row0 = blockIdx.x * BM;
    const int s    = blockIdx.y;

    float acc[32];
#pragma unroll
    for (int i = 0; i < 32; ++i) acc[i] = 0.f;

    const int tile0 = s * TPS;
    const int tile1 = (tile0 + TPS < NTILES) ? (tile0 + TPS) : NTILES;
    const int nt_   = tile1 - tile0;

    p1_load(sb, 0, tile0, X, W, row0, t);
    CP_COMMIT();

    const int mrow = wid * 32 + g;

    for (int i = 0; i < nt_; ++i) {
        if (i + 1 < nt_) p1_load(sb, (i + 1) & 1, tile0 + i + 1, X, W, row0, t);
        CP_COMMIT();
        CP_WAIT1();
        __syncthreads();

        const float* xp = reinterpret_cast<const float*>(smem + (i & 1) * P1_BUF);
        const float* wp = reinterpret_cast<const float*>(smem + (i & 1) * P1_BUF + P1_XS_BYTES);

#pragma unroll
        for (int ks = 0; ks < 4; ++ks) {
            const int kc = ks * 8;
            uint32_t a[2][4], b[4][2];
#pragma unroll
            for (int mt = 0; mt < 2; ++mt) {
                const float* ap = xp + (mrow + mt * 16) * XS_STRIDE + kc + tig;
                a[mt][0] = to_tf32(ap[0]);
                a[mt][1] = to_tf32(ap[8 * XS_STRIDE]);
                a[mt][2] = to_tf32(ap[4]);
                a[mt][3] = to_tf32(ap[8 * XS_STRIDE + 4]);
            }
#pragma unroll
            for (int nt2 = 0; nt2 < 4; ++nt2) {
                const float* bp = wp + (kc + tig) * XS_STRIDE + nt2 * 8 + g;
                b[nt2][0] = to_tf32(bp[0]);
                b[nt2][1] = to_tf32(bp[4 * XS_STRIDE]);
            }
#pragma unroll
            for (int mt = 0; mt < 2; ++mt)
#pragma unroll
                for (int nt2 = 0; nt2 < 4; ++nt2)
                    mma_tf32(&acc[(mt * 4 + nt2) * 4], a[mt], b[nt2]);
        }
        __syncthreads();
    }

#pragma unroll
    for (int mt = 0; mt < 2; ++mt) {
#pragma unroll
        for (int nt2 = 0; nt2 < 4; ++nt2) {
            const float* d = &acc[(mt * 4 + nt2) * 4];
            int r = row0 + mrow + mt * 16;
            int c = nt2 * 8 + 2 * tig;
            float2 lo = make_float2(d[0], d[1]);
            float2 hi = make_float2(d[2], d[3]);
            *reinterpret_cast<float2*>(&g_partial[((size_t)s * BATCH + r) * DIM + c]) = lo;
            *reinterpret_cast<float2*>(&g_partial[((size_t)s * BATCH + r + 8) * DIM + c]) = hi;
        }
    }
}

// =====================================================================
// Reduce partials + bias + sigmoid -> g_h (tf32-pre-rounded for pass2)
// =====================================================================
__global__ void reduce_act_kernel(const float* __restrict__ b) {
    int idx = blockIdx.x * blockDim.x + threadIdx.x;
    if (idx >= BATCH * DIM) return;
    float sum = b[idx & (DIM - 1)];
#pragma unroll
    for (int s = 0; s < NSPLIT; ++s)
        sum += g_partial[(size_t)s * BATCH * DIM + idx];
    g_h[idx] = __uint_as_float(to_tf32(sigt(sum)));
}

// =====================================================================
// Pass 2 (tf32 tensor): y = sigmoid(h @ w^T).
// CHANGE vs r7: warp owns 4 n-tiles (32 cols) instead of 8 -> bw regs
// 64->32, total regs ~70 -> 3 CTAs/SM (24 warps/SM) for +50% store/issue
// parallelism. CTA = 8 warps (4m x 2n) = 64 rows x 64 cols per chunk.
// =====================================================================
__device__ __forceinline__ void p2_load(unsigned hbase, int buf, int ib, int t) {
    const unsigned dst0 = hbase + (unsigned)buf * (P2_MROWS * HS_STRIDE * 4);
#pragma unroll
    for (int i = 0; i < 2; ++i) {
        int e   = i * P2_THREADS + t;
        int row = e >> 3;
        int q   = e & 7;
        cp16(dst0 + (unsigned)(row * HS_STRIDE + q * 4) * 4u,
             &g_h[(size_t)(ib + row) * DIM + q * 4]);
    }
}

__global__ __launch_bounds__(P2_THREADS, 3) void pass2_kernel(const float* __restrict__ W,
                                                              float* __restrict__ Y) {
    __shared__ float hs[2][P2_MROWS * HS_STRIDE];   // 18.4 KB -> 3 CTAs/SM
    const unsigned hbase = smem_u32(&hs[0][0]);

    const int t    = threadIdx.x;
    const int lane = t & 31;
    const int wid  = t >> 5;
    const int wm   = wid & 3;            // m-warp 0..3
    const int wn   = wid >> 2;           // n-warp 0..1
    const int g    = lane >> 2;
    const int tig  = lane & 3;
    const int c0   = blockIdx.x * P2_COLS + wn * 32;   // warp col base (4 n-tiles)
    const int ib0  = blockIdx.y * (BATCH / P2_YSPLIT);

    // B fragments: 4 n-tiles x 4 ks x 2 = 32 regs, loaded once per CTA
    uint32_t bw[4][4][2];
#pragma unroll
    for (int nt = 0; nt < 4; ++nt) {
        int j = c0 + nt * 8 + g;
        bool v = (j < VOCAB);
        const float* wr = W + (size_t)(v ? j : 0) * DIM;
#pragma unroll
        for (int ks = 0; ks < 4; ++ks) {
            bw[nt][ks][0] = to_tf32(v ? wr[ks * 8 + tig]     : 0.f);
            bw[nt][ks][1] = to_tf32(v ? wr[ks * 8 + tig + 4] : 0.f);
        }
    }

    p2_load(hbase, 0, ib0, t);
    CP_COMMIT();

    for (int c = 0; c < P2_CHUNKS; ++c) {
        if (c + 1 < P2_CHUNKS) p2_load(hbase, (c + 1) & 1, ib0 + (c + 1) * P2_MROWS, t);
        CP_COMMIT();
        CP_WAIT1();
        __syncthreads();

        const float* hb = hs[c & 1];
        float acc[4][4];
#pragma unroll
        for (int nt = 0; nt < 4; ++nt)
#pragma unroll
            for (int i = 0; i < 4; ++i) acc[nt][i] = 0.f;

#pragma unroll
        for (int ks = 0; ks < 4; ++ks) {
            uint32_t a[4];
            const float* ap = hb + (wm * 16 + g) * HS_STRIDE + ks * 8 + tig;
            a[0] = __float_as_uint(ap[0]);
            a[1] = __float_as_uint(ap[8 * HS_STRIDE]);
            a[2] = __float_as_uint(ap[4]);
            a[3] = __float_as_uint(ap[8 * HS_STRIDE + 4]);
#pragma unroll
            for (int nt = 0; nt < 4; ++nt)
                mma_tf32(acc[nt], a, bw[nt][ks]);
        }

        const size_t r0 = (size_t)(ib0 + c * P2_MROWS + wm * 16 + g);
#pragma unroll
        for (int nt = 0; nt < 4; ++nt) {
            int colb = c0 + nt * 8;
            if (colb < VOCAB) {          // 8 | VOCAB -> n-tile all-valid or all-invalid
                int col = colb + 2 * tig;
                float2 lo = make_float2(sigt(acc[nt][0]), sigt(acc[nt][1]));
                float2 hi = make_float2(sigt(acc[nt][2]), sigt(acc[nt][3]));
                *reinterpret_cast<float2*>(&Y[r0 * VOCAB + col])       = lo;
                *reinterpret_cast<float2*>(&Y[(r0 + 8) * VOCAB + col]) = hi;
            }
        }
        __syncthreads();
    }
}

// =====================================================================
extern "C" void kernel_launch(void* const* d_in, const int* in_sizes, int n_in,
                              void* d_out, int out_size) {
    const float* x = (const float*)d_in[0];  // [4096, 81616]
    const float* w = (const float*)d_in[1];  // [81616, 32]
    const float* b = (const float*)d_in[2];  // [32]
    float* y = (float*)d_out;                // [4096, 81616]

    cudaFuncSetAttribute(pass1_kernel, cudaFuncAttributeMaxDynamicSharedMemorySize, P1_SMEM);

    dim3 g1(ROWBLOCKS, NSPLIT);
    pass1_kernel<<<g1, P1_THREADS, P1_SMEM>>>(x, w);

    reduce_act_kernel<<<(BATCH * DIM + 255) / 256, 256>>>(b);

    dim3 g2((VOCAB + P2_COLS - 1) / P2_COLS, P2_YSPLIT);
    pass2_kernel<<<g2, P2_THREADS>>>(w, y);
}

// round 17
// speedup vs baseline: 1.1137x; 1.0391x over previous
#include <cuda_runtime.h>
#include <cstdint>

#define VOCAB 81616
#define DIM 32
#define BATCH 4096

typedef unsigned long long u64;

// ------- pass 1 config: BM=256, 8 warps, 3-stage compact-swizzle, 2 CTAs/SM -------
#define BM 256
#define BK 32
#define NSPLIT 18
#define NTILES ((VOCAB + BK - 1) / BK)        // 2551
#define TPS ((NTILES + NSPLIT - 1) / NSPLIT)  // 142
#define ROWBLOCKS (BATCH / BM)                // 16
#define P1_THREADS 256
#define P1_STAGES 3

#define WS_STRIDE 36
#define P1_XS_BYTES (BM * BK * 4)             // 32768: 128B rows, XOR-swizzled
#define P1_WS_BYTES (BK * WS_STRIDE * 4)      // 4608
#define P1_BUF (P1_XS_BYTES + P1_WS_BYTES)    // 37376
#define P1_SMEM (P1_STAGES * P1_BUF)          // 112128 -> 2 CTAs/SM (219KB/228KB)

// ---------------- pass 2 config (r7-proven exact) ----------------
#define P2_THREADS 256
#define P2_MROWS 64
#define P2_COLS 128
#define P2_YSPLIT 4
#define P2_CHUNKS ((BATCH / P2_YSPLIT) / P2_MROWS)  // 16
#define HS_STRIDE 36

// Scratch (no cudaMalloc allowed — device globals)
__device__ __align__(16) float g_partial[NSPLIT * BATCH * DIM];  // 9.4 MB
__device__ __align__(16) float g_h[BATCH * DIM];                 // 512 KB (tf32-rounded)

// ---------------- helpers ----------------
__device__ __forceinline__ float sigt(float x) {
    float t;
    asm("tanh.approx.f32 %0, %1;" : "=f"(t) : "f"(x * 0.5f));
    return fmaf(0.5f, t, 0.5f);
}

__device__ __forceinline__ unsigned smem_u32(const void* p) {
    unsigned a;
    asm("{ .reg .u64 t; cvta.to.shared.u64 t, %1; cvt.u32.u64 %0, t; }" : "=r"(a) : "l"(p));
    return a;
}

__device__ __forceinline__ void cp16z(unsigned dst, const void* src, unsigned sz) {
    asm volatile("cp.async.cg.shared.global [%0], [%1], 16, %2;" :: "r"(dst), "l"(src), "r"(sz));
}
__device__ __forceinline__ void cp4(unsigned dst, const void* src, unsigned sz) {
    asm volatile("cp.async.ca.shared.global [%0], [%1], 4, %2;" :: "r"(dst), "l"(src), "r"(sz));
}
__device__ __forceinline__ void cp16(unsigned dst, const void* src) {
    asm volatile("cp.async.ca.shared.global [%0], [%1], 16;" :: "r"(dst), "l"(src));
}
#define CP_COMMIT() asm volatile("cp.async.commit_group;")
#define CP_WAIT1()  asm volatile("cp.async.wait_group 1;")
#define CP_WAIT2()  asm volatile("cp.async.wait_group 2;")

__device__ __forceinline__ uint32_t to_tf32(float f) {
    uint32_t r;
    asm("cvt.rna.tf32.f32 %0, %1;" : "=r"(r) : "f"(f));
    return r;
}

__device__ __forceinline__ void mma_tf32(float* d, const uint32_t* a, const uint32_t* b) {
    asm("mma.sync.aligned.m16n8k8.row.col.f32.tf32.tf32.f32 "
        "{%0,%1,%2,%3}, {%4,%5,%6,%7}, {%8,%9}, {%0,%1,%2,%3};"
        : "+f"(d[0]), "+f"(d[1]), "+f"(d[2]), "+f"(d[3])
        : "r"(a[0]), "r"(a[1]), "r"(a[2]), "r"(a[3]), "r"(b[0]), "r"(b[1]));
}

// =====================================================================
// Pass 1 (tf32 tensor): partial[s] = x[rows] @ w over this split's chunk.
// r10 structure (BM=256, 8 warps, 2 CTAs/SM) with ONE change: 3-stage
// pipeline enabled by the compact XOR-swizzled x layout (128B rows;
// 16B chunk u of row r lives at u^(r&7); a-frag LDS bank =
// ((2ks)^g)*4+tig -> all 32 distinct; verified correct in r14).
// w staged in smem (stride 36) exactly as in the 258us baseline.
// =====================================================================
__device__ __forceinline__ void p1_load(unsigned sb, int buf, int tile,
                                        const float* __restrict__ X,
                                        const float* __restrict__ W,
                                        int row0, int t) {
    const int k0 = tile * BK;
    const unsigned xbase = sb + (unsigned)buf * P1_BUF;
    const unsigned wbase = xbase + P1_XS_BYTES;

    // x: 256 rows x 8 float4 -> 8 cp16 per thread; lanes 0..7 cover one row
    const int u   = t & 7;             // chunk (cols 4u..4u+3)
    const int r0  = t >> 3;            // 0..31
    const int key = r0 & 7;            // rows step by 32 -> key constant per thread
    const int gk  = k0 + 4 * u;
    const unsigned szx = (gk < VOCAB) ? 16u : 0u;   // 0 -> zero-fill
    const float* srcx = (gk < VOCAB) ? (X + (size_t)(row0 + r0) * VOCAB + gk) : X;
    const unsigned dst0 = xbase + (unsigned)((u ^ key) * 16);
#pragma unroll
    for (int i = 0; i < 8; ++i) {
        int row = i * 32 + r0;
        cp16z(dst0 + (unsigned)(row * 128), srcx, szx);
        srcx += (size_t)32 * VOCAB;
    }

    // w: 32 k-rows x 32 j, native layout ws[k][j]; 4 cp4 per thread
    const int j  = t & 31;
    const int kb = t >> 5;             // 0..7
#pragma unroll
    for (int i = 0; i < 4; ++i) {
        int kk = kb + i * 8;
        int g  = k0 + kk;
        unsigned sz = (g < VOCAB) ? 4u : 0u;
        const float* src = (g < VOCAB) ? (W + (size_t)g * DIM + j) : W;
        cp4(wbase + (unsigned)(kk * WS_STRIDE + j) * 4u, src, sz);
    }
}

__global__ __launch_bounds__(P1_THREADS, 2) void pass1_kernel(const float* __restrict__ X,
                                                              const float* __restrict__ W) {
    extern __shared__ char smem[];
    const unsigned sb = smem_u32(smem);

    const int t    = threadIdx.x;
    const int lane = t & 31;
    const int wid  = t >> 5;           // 0..7 -> m-slab
    const int g    = lane >> 2;
    const int tig  = lane & 3;
    const int row0 = blockIdx.x * BM;
    const int s    = blockIdx.y;

    float acc[32];
#pragma unroll
    for (int i = 0; i < 32; ++i) acc[i] = 0.f;

    const int tile0 = s * TPS;
    const int tile1 = (tile0 + TPS < NTILES) ? (tile0 + TPS) : NTILES;
    const int nt_   = tile1 - tile0;

    // prologue: 2 tiles in flight
    p1_load(sb, 0, tile0, X, W, row0, t);
    CP_COMMIT();
    if (nt_ > 1) p1_load(sb, 1, tile0 + 1, X, W, row0, t);
    CP_COMMIT();

    const int mrow = wid * 32 + g;

    for (int i = 0; i < nt_; ++i) {
        if (i + 2 < nt_) p1_load(sb, (i + 2) % P1_STAGES, tile0 + i + 2, X, W, row0, t);
        CP_COMMIT();
        CP_WAIT2();                     // stage i complete (<=2 groups pending)
        __syncthreads();

        const int buf = i % P1_STAGES;
        const float* xp = reinterpret_cast<const float*>(smem + buf * P1_BUF);
        const float* wp = reinterpret_cast<const float*>(smem + buf * P1_BUF + P1_XS_BYTES);

#pragma unroll
        for (int ks = 0; ks < 4; ++ks) {
            // a-frags from swizzled smem: chunk = (2ks[,+1]) ^ g, elem tig
            const int off0 = ((2 * ks) ^ g) * 4 + tig;
            const int off1 = ((2 * ks + 1) ^ g) * 4 + tig;
            const int kc = ks * 8;
            uint32_t a[2][4], b[4][2];
#pragma unroll
            for (int mt = 0; mt < 2; ++mt) {
                const float* ap = xp + (mrow + mt * 16) * 32;
                a[mt][0] = to_tf32(ap[off0]);
                a[mt][1] = to_tf32(ap[8 * 32 + off0]);
                a[mt][2] = to_tf32(ap[off1]);
                a[mt][3] = to_tf32(ap[8 * 32 + off1]);
            }
#pragma unroll
            for (int nt2 = 0; nt2 < 4; ++nt2) {
                const float* bp = wp + (kc + tig) * WS_STRIDE + nt2 * 8 + g;
                b[nt2][0] = to_tf32(bp[0]);
                b[nt2][1] = to_tf32(bp[4 * WS_STRIDE]);
            }
#pragma unroll
            for (int mt = 0; mt < 2; ++mt)
#pragma unroll
                for (int nt2 = 0; nt2 < 4; ++nt2)
                    mma_tf32(&acc[(mt * 4 + nt2) * 4], a[mt], b[nt2]);
        }
        __syncthreads();
    }

#pragma unroll
    for (int mt = 0; mt < 2; ++mt) {
#pragma unroll
        for (int nt2 = 0; nt2 < 4; ++nt2) {
            const float* d = &acc[(mt * 4 + nt2) * 4];
            int r = row0 + mrow + mt * 16;
            int c = nt2 * 8 + 2 * tig;
            float2 lo = make_float2(d[0], d[1]);
            float2 hi = make_float2(d[2], d[3]);
            *reinterpret_cast<float2*>(&g_partial[((size_t)s * BATCH + r) * DIM + c]) = lo;
            *reinterpret_cast<float2*>(&g_partial[((size_t)s * BATCH + r + 8) * DIM + c]) = hi;
        }
    }
}

// =====================================================================
// Reduce partials + bias + sigmoid -> g_h (tf32-pre-rounded for pass2)
// =====================================================================
__global__ void reduce_act_kernel(const float* __restrict__ b) {
    int idx = blockIdx.x * blockDim.x + threadIdx.x;
    if (idx >= BATCH * DIM) return;
    float sum = b[idx & (DIM - 1)];
#pragma unroll
    for (int s = 0; s < NSPLIT; ++s)
        sum += g_partial[(size_t)s * BATCH * DIM + idx];
    g_h[idx] = __uint_as_float(to_tf32(sigt(sum)));
}

// =====================================================================
// Pass 2 (tf32 tensor): y = sigmoid(h @ w^T)  [r7-proven exact]
// =====================================================================
__device__ __forceinline__ void p2_load(unsigned hbase, int buf, int ib, int t) {
    const unsigned dst0 = hbase + (unsigned)buf * (P2_MROWS * HS_STRIDE * 4);
#pragma unroll
    for (int i = 0; i < 2; ++i) {
        int e   = i * P2_THREADS + t;
        int row = e >> 3;
        int q   = e & 7;
        cp16(dst0 + (unsigned)(row * HS_STRIDE + q * 4) * 4u,
             &g_h[(size_t)(ib + row) * DIM + q * 4]);
    }
}

__global__ __launch_bounds__(P2_THREADS, 2) void pass2_kernel(const float* __restrict__ W,
                                                              float* __restrict__ Y) {
    __shared__ float hs[2][P2_MROWS * HS_STRIDE];
    const unsigned hbase = smem_u32(&hs[0][0]);

    const int t    = threadIdx.x;
    const int lane = t & 31;
    const int wid  = t >> 5;
    const int wm   = wid & 3;
    const int wn   = wid >> 2;
    const int g    = lane >> 2;
    const int tig  = lane & 3;
    const int c0   = blockIdx.x * P2_COLS + wn * 64;
    const int ib0  = blockIdx.y * (BATCH / P2_YSPLIT);

    uint32_t bw[8][4][2];
#pragma unroll
    for (int nt = 0; nt < 8; ++nt) {
        int j = c0 + nt * 8 + g;
        bool v = (j < VOCAB);
        const float* wr = W + (size_t)(v ? j : 0) * DIM;
#pragma unroll
        for (int ks = 0; ks < 4; ++ks) {
            bw[nt][ks][0] = to_tf32(v ? wr[ks * 8 + tig]     : 0.f);
            bw[nt][ks][1] = to_tf32(v ? wr[ks * 8 + tig + 4] : 0.f);
        }
    }

    p2_load(hbase, 0, ib0, t);
    CP_COMMIT();

    for (int c = 0; c < P2_CHUNKS; ++c) {
        if (c + 1 < P2_CHUNKS) p2_load(hbase, (c + 1) & 1, ib0 + (c + 1) * P2_MROWS, t);
        CP_COMMIT();
        CP_WAIT1();
        __syncthreads();

        const float* hb = hs[c & 1];
        float acc[8][4];
#pragma unroll
        for (int nt = 0; nt < 8; ++nt)
#pragma unroll
            for (int i = 0; i < 4; ++i) acc[nt][i] = 0.f;

#pragma unroll
        for (int ks = 0; ks < 4; ++ks) {
            uint32_t a[4];
            const float* ap = hb + (wm * 16 + g) * HS_STRIDE + ks * 8 + tig;
            a[0] = __float_as_uint(ap[0]);
            a[1] = __float_as_uint(ap[8 * HS_STRIDE]);
            a[2] = __float_as_uint(ap[4]);
            a[3] = __float_as_uint(ap[8 * HS_STRIDE + 4]);
#pragma unroll
            for (int nt = 0; nt < 8; ++nt)
                mma_tf32(acc[nt], a, bw[nt][ks]);
        }

        const size_t r0 = (size_t)(ib0 + c * P2_MROWS + wm * 16 + g);
#pragma unroll
        for (int nt = 0; nt < 8; ++nt) {
            int colb = c0 + nt * 8;
            if (colb < VOCAB) {
                int col = colb + 2 * tig;
                float2 lo = make_float2(sigt(acc[nt][0]), sigt(acc[nt][1]));
                float2 hi = make_float2(sigt(acc[nt][2]), sigt(acc[nt][3]));
                *reinterpret_cast<float2*>(&Y[r0 * VOCAB + col])       = lo;
                *reinterpret_cast<float2*>(&Y[(r0 + 8) * VOCAB + col]) = hi;
            }
        }
        __syncthreads();
    }
}

// =====================================================================
extern "C" void kernel_launch(void* const* d_in, const int* in_sizes, int n_in,
                              void* d_out, int out_size) {
    const float* x = (const float*)d_in[0];  // [4096, 81616]
    const float* w = (const float*)d_in[1];  // [81616, 32]
    const float* b = (const float*)d_in[2];  // [32]
    float* y = (float*)d_out;                // [4096, 81616]

    cudaFuncSetAttribute(pass1_kernel, cudaFuncAttributeMaxDynamicSharedMemorySize, P1_SMEM);

    dim3 g1(ROWBLOCKS, NSPLIT);
    pass1_kernel<<<g1, P1_THREADS, P1_SMEM>>>(x, w);

    reduce_act_kernel<<<(BATCH * DIM + 255) / 256, 256>>>(b);

    dim3 g2((VOCAB + P2_COLS - 1) / P2_COLS, P2_YSPLIT);
    pass2_kernel<<<g2, P2_THREADS>>>(w, y);
}